// round 9
// baseline (speedup 1.0000x reference)
#include <cuda_runtime.h>
#include <math.h>

#define H_DIM 1024
#define NAG 256
#define BTOK 8192
#define NTH 256
#define SB 32
#define LN_EPS 1e-5f
#define ALPHA_MAX 5.0f

// ---- global scratch ----
__device__ int g_cnt[NAG];
__device__ int g_toks[NAG][BTOK];

__global__ void build_lists_kernel(const int* __restrict__ ids) {
    int i = blockIdx.x * blockDim.x + threadIdx.x;
    if (i < BTOK) {
        int a = ids[i] & (NAG - 1);
        int p = atomicAdd(&g_cnt[a], 1);
        g_toks[a][p] = i;
    }
}

// ---- cp.async helpers ----
__device__ __forceinline__ void cp16(void* s, const void* g) {
    unsigned sa = (unsigned)__cvta_generic_to_shared(s);
    asm volatile("cp.async.cg.shared.global [%0], [%1], 16;\n" :: "r"(sa), "l"(g));
}
#define CP_COMMIT() asm volatile("cp.async.commit_group;\n" ::: "memory")
#define CP_WAIT1()  asm volatile("cp.async.wait_group 1;\n" ::: "memory")
#define CP_WAIT0()  asm volatile("cp.async.wait_group 0;\n" ::: "memory")

// SMEM (floats): ubuf 2x4096 @0 (U/V chunk ping-pong, 2x16KB)
//                hbuf 2x4096 @8192 (h chunk ping-pong, 2x16KB)
//                stoks 32 int @16384
#define OFF_HB 8192
#define OFF_TK 16384
#define SMEM_BYTES ((16384 + 32) * 4)

__global__ __launch_bounds__(NTH, 2)
void div_inject_kernel(const float* __restrict__ h,
                       const float* __restrict__ log_alpha,
                       const float* __restrict__ gamma,
                       const float* __restrict__ beta,
                       const float* __restrict__ pu,
                       const float* __restrict__ pv,
                       float*       __restrict__ out)
{
    extern __shared__ float smem[];
    float* ubuf  = smem;
    float* hbuf  = smem + OFF_HB;
    int*   stoks = (int*)(smem + OFF_TK);
    __shared__ int s_total;

    const int tid  = threadIdx.x;
    const int lane = tid & 31;
    const int wid  = tid >> 5;       // 0..7
    const int agent = blockIdx.x;

    if (tid == 0) { s_total = g_cnt[agent]; g_cnt[agent] = 0; }
    __syncthreads();
    const int total = s_total;
    if (total == 0) return;

    const float alpha = fminf(expf(log_alpha[0]), ALPHA_MAX);
    const int* toks = g_toks[agent];
    const float4* pu4 = (const float4*)pu + (size_t)agent * 8192;  // U chunks contiguous
    const float4* pv4 = (const float4*)pv + (size_t)agent * 8192;  // V row stride 256 f4
    const float4* h4  = (const float4*)h;
    float4* out4 = (float4*)out;

    for (int base = 0; base < total; base += SB) {
        const int nb = min(SB, total - base);
        if (tid < SB) stoks[tid] = toks[base + min(tid, nb - 1)];
        __syncthreads();

        // token ownership (fixed A/B mapping keeps inter in registers)
        int  gt[4]; bool vd[4]; int tk[4];
        #pragma unroll
        for (int i = 0; i < 4; ++i) {
            tk[i] = 4 * wid + i;
            vd[i] = tk[i] < nb;
            gt[i] = stoks[tk[i]];
        }

        // ---- stage group 0: U chunk0 + h chunk0 ----
        {
            float4* du = (float4*)ubuf;
            float4* dh = (float4*)hbuf;
            #pragma unroll
            for (int i = 0; i < 4; ++i) {
                const int idx = tid + i * 256;
                cp16(du + idx, pu4 + idx);
                const int tok = idx >> 5, cc = idx & 31;
                cp16(dh + idx, h4 + (size_t)stoks[tok] * 256 + cc);
            }
            CP_COMMIT();
        }

        // ================= phase A =================
        float4 a0 = make_float4(0.f,0.f,0.f,0.f);
        float4 a1 = make_float4(0.f,0.f,0.f,0.f);
        float4 a2 = make_float4(0.f,0.f,0.f,0.f);
        float4 a3 = make_float4(0.f,0.f,0.f,0.f);

        #pragma unroll 1
        for (int c = 0; c < 8; ++c) {
            const int nxt = (c + 1) & 1;
            if (c < 7) {
                float4* du = (float4*)(ubuf + nxt * 4096);
                float4* dh = (float4*)(hbuf + nxt * 4096);
                #pragma unroll
                for (int i = 0; i < 4; ++i) {
                    const int idx = tid + i * 256;
                    cp16(du + idx, pu4 + (c + 1) * 1024 + idx);
                    const int tok = idx >> 5, cc = idx & 31;
                    cp16(dh + idx, h4 + (size_t)stoks[tok] * 256 + (c + 1) * 32 + cc);
                }
            } else {
                // cross-phase prefetch: V chunk0 into ubuf[nxt]
                float4* dv = (float4*)(ubuf + nxt * 4096);
                #pragma unroll
                for (int i = 0; i < 4; ++i) {
                    const int idx = tid + i * 256;
                    const int r = idx >> 5, cc = idx & 31;
                    cp16(dv + idx, pv4 + r * 256 + cc);
                }
            }
            CP_COMMIT();
            CP_WAIT1();
            __syncthreads();

            const float*  ub = ubuf + (c & 1) * 4096;
            const float4* hb = (const float4*)(hbuf + (c & 1) * 4096);
            const float4* hp0 = hb + tk[0] * 32;
            const float4* hp1 = hb + tk[1] * 32;
            const float4* hp2 = hb + tk[2] * 32;
            const float4* hp3 = hb + tk[3] * 32;

            #pragma unroll 8
            for (int k4 = 0; k4 < 32; ++k4) {
                float4 x0 = hp0[k4];
                float4 x1 = hp1[k4];
                float4 x2 = hp2[k4];
                float4 x3 = hp3[k4];
                const float* up = ub + k4 * 128 + lane;
                float u0 = up[0];
                float u1 = up[32];
                float u2 = up[64];
                float u3 = up[96];
                a0.x = fmaf(x0.x,u0,a0.x); a0.y = fmaf(x0.y,u1,a0.y);
                a0.z = fmaf(x0.z,u2,a0.z); a0.w = fmaf(x0.w,u3,a0.w);
                a1.x = fmaf(x1.x,u0,a1.x); a1.y = fmaf(x1.y,u1,a1.y);
                a1.z = fmaf(x1.z,u2,a1.z); a1.w = fmaf(x1.w,u3,a1.w);
                a2.x = fmaf(x2.x,u0,a2.x); a2.y = fmaf(x2.y,u1,a2.y);
                a2.z = fmaf(x2.z,u2,a2.z); a2.w = fmaf(x2.w,u3,a2.w);
                a3.x = fmaf(x3.x,u0,a3.x); a3.y = fmaf(x3.y,u1,a3.y);
                a3.z = fmaf(x3.z,u2,a3.z); a3.w = fmaf(x3.w,u3,a3.w);
            }
            __syncthreads();
        }
        // intermediates stay in registers: lane = r
        const float iv0 = (a0.x + a0.y) + (a0.z + a0.w);
        const float iv1 = (a1.x + a1.y) + (a1.z + a1.w);
        const float iv2 = (a2.x + a2.y) + (a2.z + a2.w);
        const float iv3 = (a3.x + a3.y) + (a3.z + a3.w);

        // ================= phase B =================
        float s0=0.f, s1=0.f, s2=0.f, s3=0.f;
        float q0=0.f, q1=0.f, q2=0.f, q3=0.f;

        #pragma unroll 1
        for (int c = 0; c < 8; ++c) {
            if (c < 7) {
                float4* dv = (float4*)(ubuf + ((c + 1) & 1) * 4096);
                #pragma unroll
                for (int i = 0; i < 4; ++i) {
                    const int idx = tid + i * 256;
                    const int r = idx >> 5, cc = idx & 31;
                    cp16(dv + idx, pv4 + r * 256 + (c + 1) * 32 + cc);
                }
                CP_COMMIT();
                CP_WAIT1();
            } else {
                CP_WAIT0();
            }
            __syncthreads();

            const float4* vb = (const float4*)(ubuf + (c & 1) * 4096);
            float4 p0 = make_float4(0.f,0.f,0.f,0.f);
            float4 p1 = make_float4(0.f,0.f,0.f,0.f);
            float4 p2 = make_float4(0.f,0.f,0.f,0.f);
            float4 p3 = make_float4(0.f,0.f,0.f,0.f);

            #pragma unroll 4
            for (int r = 0; r < 32; ++r) {
                const float b0 = __shfl_sync(0xffffffffu, iv0, r);
                const float b1 = __shfl_sync(0xffffffffu, iv1, r);
                const float b2 = __shfl_sync(0xffffffffu, iv2, r);
                const float b3 = __shfl_sync(0xffffffffu, iv3, r);
                float4 v = vb[r * 32 + lane];
                p0.x = fmaf(b0,v.x,p0.x); p0.y = fmaf(b0,v.y,p0.y);
                p0.z = fmaf(b0,v.z,p0.z); p0.w = fmaf(b0,v.w,p0.w);
                p1.x = fmaf(b1,v.x,p1.x); p1.y = fmaf(b1,v.y,p1.y);
                p1.z = fmaf(b1,v.z,p1.z); p1.w = fmaf(b1,v.w,p1.w);
                p2.x = fmaf(b2,v.x,p2.x); p2.y = fmaf(b2,v.y,p2.y);
                p2.z = fmaf(b2,v.z,p2.z); p2.w = fmaf(b2,v.w,p2.w);
                p3.x = fmaf(b3,v.x,p3.x); p3.y = fmaf(b3,v.y,p3.y);
                p3.z = fmaf(b3,v.z,p3.z); p3.w = fmaf(b3,v.w,p3.w);
            }

            // residual d = h + alpha*p -> unnormalized store to out; sums in regs
            if (vd[0]) {
                float4 hv = h4[(size_t)gt[0] * 256 + c * 32 + lane];
                float4 d;
                d.x = fmaf(alpha,p0.x,hv.x); d.y = fmaf(alpha,p0.y,hv.y);
                d.z = fmaf(alpha,p0.z,hv.z); d.w = fmaf(alpha,p0.w,hv.w);
                s0 += (d.x + d.y) + (d.z + d.w);
                q0 += d.x*d.x + d.y*d.y + d.z*d.z + d.w*d.w;
                out4[(size_t)gt[0] * 256 + c * 32 + lane] = d;
            }
            if (vd[1]) {
                float4 hv = h4[(size_t)gt[1] * 256 + c * 32 + lane];
                float4 d;
                d.x = fmaf(alpha,p1.x,hv.x); d.y = fmaf(alpha,p1.y,hv.y);
                d.z = fmaf(alpha,p1.z,hv.z); d.w = fmaf(alpha,p1.w,hv.w);
                s1 += (d.x + d.y) + (d.z + d.w);
                q1 += d.x*d.x + d.y*d.y + d.z*d.z + d.w*d.w;
                out4[(size_t)gt[1] * 256 + c * 32 + lane] = d;
            }
            if (vd[2]) {
                float4 hv = h4[(size_t)gt[2] * 256 + c * 32 + lane];
                float4 d;
                d.x = fmaf(alpha,p2.x,hv.x); d.y = fmaf(alpha,p2.y,hv.y);
                d.z = fmaf(alpha,p2.z,hv.z); d.w = fmaf(alpha,p2.w,hv.w);
                s2 += (d.x + d.y) + (d.z + d.w);
                q2 += d.x*d.x + d.y*d.y + d.z*d.z + d.w*d.w;
                out4[(size_t)gt[2] * 256 + c * 32 + lane] = d;
            }
            if (vd[3]) {
                float4 hv = h4[(size_t)gt[3] * 256 + c * 32 + lane];
                float4 d;
                d.x = fmaf(alpha,p3.x,hv.x); d.y = fmaf(alpha,p3.y,hv.y);
                d.z = fmaf(alpha,p3.z,hv.z); d.w = fmaf(alpha,p3.w,hv.w);
                s3 += (d.x + d.y) + (d.z + d.w);
                q3 += d.x*d.x + d.y*d.y + d.z*d.z + d.w*d.w;
                out4[(size_t)gt[3] * 256 + c * 32 + lane] = d;
            }
            __syncthreads();
        }

        // ---- LN finalize: butterfly reduce all 8 sums ----
        #pragma unroll
        for (int o = 16; o > 0; o >>= 1) {
            s0 += __shfl_xor_sync(0xffffffffu, s0, o);
            q0 += __shfl_xor_sync(0xffffffffu, q0, o);
            s1 += __shfl_xor_sync(0xffffffffu, s1, o);
            q1 += __shfl_xor_sync(0xffffffffu, q1, o);
            s2 += __shfl_xor_sync(0xffffffffu, s2, o);
            q2 += __shfl_xor_sync(0xffffffffu, q2, o);
            s3 += __shfl_xor_sync(0xffffffffu, s3, o);
            q3 += __shfl_xor_sync(0xffffffffu, q3, o);
        }
        float mean[4], rstd[4];
        {
            const float ms0 = s0 * (1.0f/H_DIM), ms1 = s1 * (1.0f/H_DIM);
            const float ms2 = s2 * (1.0f/H_DIM), ms3 = s3 * (1.0f/H_DIM);
            mean[0]=ms0; mean[1]=ms1; mean[2]=ms2; mean[3]=ms3;
            rstd[0] = rsqrtf(q0*(1.0f/H_DIM) - ms0*ms0 + LN_EPS);
            rstd[1] = rsqrtf(q1*(1.0f/H_DIM) - ms1*ms1 + LN_EPS);
            rstd[2] = rsqrtf(q2*(1.0f/H_DIM) - ms2*ms2 + LN_EPS);
            rstd[3] = rsqrtf(q3*(1.0f/H_DIM) - ms3*ms3 + LN_EPS);
        }

        // ---- pass 2: normalize in place (warp-local; d is L2-hot) ----
        const float4* g4 = (const float4*)gamma;
        const float4* b4 = (const float4*)beta;
        #pragma unroll
        for (int i = 0; i < 4; ++i) {
            if (!vd[i]) continue;
            const float mn = mean[i], rs = rstd[i];
            float4* op = out4 + (size_t)gt[i] * 256 + lane;
            #pragma unroll
            for (int c = 0; c < 8; ++c) {
                float4 d = op[c * 32];
                float4 g = g4[c * 32 + lane];
                float4 bb = b4[c * 32 + lane];
                float4 o_;
                o_.x = (d.x - mn) * rs * g.x + bb.x;
                o_.y = (d.y - mn) * rs * g.y + bb.y;
                o_.z = (d.z - mn) * rs * g.z + bb.z;
                o_.w = (d.w - mn) * rs * g.w + bb.w;
                op[c * 32] = o_;
            }
        }
        __syncthreads();   // stoks/buffers reuse safety for next batch
    }
}

extern "C" void kernel_launch(void* const* d_in, const int* in_sizes, int n_in,
                              void* d_out, int out_size)
{
    const float* h     = (const float*)d_in[0];
    const float* la    = (const float*)d_in[1];
    const float* gamma = (const float*)d_in[2];
    const float* beta  = (const float*)d_in[3];
    const float* pu    = (const float*)d_in[4];
    const float* pv    = (const float*)d_in[5];
    const int*   ids   = (const int*)d_in[6];
    float*       out   = (float*)d_out;

    build_lists_kernel<<<(BTOK + 255) / 256, 256>>>(ids);

    cudaFuncSetAttribute(div_inject_kernel,
                         cudaFuncAttributeMaxDynamicSharedMemorySize, SMEM_BYTES);
    div_inject_kernel<<<NAG, NTH, SMEM_BYTES>>>(h, la, gamma, beta, pu, pv, out);
}

// round 10
// speedup vs baseline: 1.2381x; 1.2381x over previous
#include <cuda_runtime.h>
#include <math.h>

#define H_DIM 1024
#define NAG 256
#define BTOK 8192
#define NTH 256
#define SB 32
#define GRID_MAIN 296
#define LN_EPS 1e-5f
#define ALPHA_MAX 5.0f

// ---- global scratch ----
__device__ int g_cnt[NAG];        // zeroed by build_items after read
__device__ int g_cnt2[NAG];       // stable copy for main kernel
__device__ int g_toks[NAG][BTOK];
__device__ int g_items[1024];     // agent | (batch<<8)
__device__ int g_nitems;
__device__ int g_ifetch;

__global__ void build_lists_kernel(const int* __restrict__ ids) {
    int i = blockIdx.x * blockDim.x + threadIdx.x;
    if (i == 0) { g_nitems = 0; g_ifetch = 0; }
    if (i < BTOK) {
        int a = ids[i] & (NAG - 1);
        int p = atomicAdd(&g_cnt[a], 1);
        g_toks[a][p] = i;
    }
}

__global__ void build_items_kernel() {
    int a = threadIdx.x;
    int n = g_cnt[a];
    g_cnt[a] = 0;          // reset for next replay
    g_cnt2[a] = n;
    int nit = (n + SB - 1) / SB;
    for (int b = 0; b < nit; ++b) {
        int p = atomicAdd(&g_nitems, 1);
        g_items[p] = a | (b << 8);
    }
}

// ---- cp.async helpers ----
__device__ __forceinline__ void cp16(void* s, const void* g) {
    unsigned sa = (unsigned)__cvta_generic_to_shared(s);
    asm volatile("cp.async.cg.shared.global [%0], [%1], 16;\n" :: "r"(sa), "l"(g));
}
#define CP_COMMIT() asm volatile("cp.async.commit_group;\n" ::: "memory")
#define CP_WAIT1()  asm volatile("cp.async.wait_group 1;\n" ::: "memory")
#define CP_WAIT0()  asm volatile("cp.async.wait_group 0;\n" ::: "memory")

// SMEM: ubuf 2x4096 @0, hbuf 2x4096 @8192, stoks @16384
#define OFF_HB 8192
#define OFF_TK 16384
#define SMEM_BYTES ((16384 + 32) * 4)

__global__ __launch_bounds__(NTH, 2)
void div_inject_kernel(const float* __restrict__ h,
                       const float* __restrict__ log_alpha,
                       const float* __restrict__ gamma,
                       const float* __restrict__ beta,
                       const float* __restrict__ pu,
                       const float* __restrict__ pv,
                       float*       __restrict__ out)
{
    extern __shared__ float smem[];
    float* ubuf  = smem;
    float* hbuf  = smem + OFF_HB;
    int*   stoks = (int*)(smem + OFF_TK);
    __shared__ int s_item;

    const int tid  = threadIdx.x;
    const int lane = tid & 31;
    const int wid  = tid >> 5;

    const float alpha = fminf(expf(log_alpha[0]), ALPHA_MAX);
    const float4* h4  = (const float4*)h;
    float4* out4 = (float4*)out;
    const int nitems = g_nitems;

    for (;;) {
        if (tid == 0) s_item = atomicAdd(&g_ifetch, 1);
        __syncthreads();
        const int it = s_item;
        if (it >= nitems) break;

        const int info  = g_items[it];
        const int agent = info & 255;
        const int base  = (info >> 8) * SB;
        const int nb    = min(SB, g_cnt2[agent] - base);
        const int* toks = g_toks[agent];
        const float4* pu4 = (const float4*)pu + (size_t)agent * 8192;
        const float4* pv4 = (const float4*)pv + (size_t)agent * 8192;

        if (tid < SB) stoks[tid] = toks[base + min(tid, nb - 1)];
        __syncthreads();

        const bool gvalid = (4 * wid) < nb;   // warp-group has >=1 valid token
        int  gt[4]; bool vd[4]; int tk[4];
        #pragma unroll
        for (int i = 0; i < 4; ++i) {
            tk[i] = min(4 * wid + i, nb - 1);
            vd[i] = (4 * wid + i) < nb;
            gt[i] = stoks[tk[i]];
        }

        // ---- stage group 0: U chunk0 + h chunk0 ----
        {
            float4* du = (float4*)ubuf;
            float4* dh = (float4*)hbuf;
            #pragma unroll
            for (int i = 0; i < 4; ++i) {
                const int idx = tid + i * 256;
                cp16(du + idx, pu4 + idx);
                const int tok = idx >> 5, cc = idx & 31;
                cp16(dh + idx, h4 + (size_t)stoks[tok] * 256 + cc);
            }
            CP_COMMIT();
        }

        // ================= phase A =================
        float4 a0 = make_float4(0.f,0.f,0.f,0.f);
        float4 a1 = make_float4(0.f,0.f,0.f,0.f);
        float4 a2 = make_float4(0.f,0.f,0.f,0.f);
        float4 a3 = make_float4(0.f,0.f,0.f,0.f);

        #pragma unroll 1
        for (int c = 0; c < 8; ++c) {
            const int nxt = (c + 1) & 1;
            if (c < 7) {
                float4* du = (float4*)(ubuf + nxt * 4096);
                float4* dh = (float4*)(hbuf + nxt * 4096);
                #pragma unroll
                for (int i = 0; i < 4; ++i) {
                    const int idx = tid + i * 256;
                    cp16(du + idx, pu4 + (c + 1) * 1024 + idx);
                    const int tok = idx >> 5, cc = idx & 31;
                    cp16(dh + idx, h4 + (size_t)stoks[tok] * 256 + (c + 1) * 32 + cc);
                }
            } else {
                float4* dv = (float4*)(ubuf + nxt * 4096);
                #pragma unroll
                for (int i = 0; i < 4; ++i) {
                    const int idx = tid + i * 256;
                    const int r = idx >> 5, cc = idx & 31;
                    cp16(dv + idx, pv4 + r * 256 + cc);
                }
            }
            CP_COMMIT();
            CP_WAIT1();
            __syncthreads();

            if (gvalid) {
                const float*  ubl = ubuf + (c & 1) * 4096 + lane;
                const float4* hb = (const float4*)(hbuf + (c & 1) * 4096);
                const float4* hp0 = hb + tk[0] * 32;
                const float4* hp1 = hb + tk[1] * 32;
                const float4* hp2 = hb + tk[2] * 32;
                const float4* hp3 = hb + tk[3] * 32;

                // 1-deep software pipeline
                float4 x0 = hp0[0], x1 = hp1[0], x2 = hp2[0], x3 = hp3[0];
                float u0 = ubl[0], u1 = ubl[32], u2 = ubl[64], u3 = ubl[96];

                #pragma unroll 4
                for (int k4 = 0; k4 < 32; ++k4) {
                    float4 cx0 = x0, cx1 = x1, cx2 = x2, cx3 = x3;
                    float cu0 = u0, cu1 = u1, cu2 = u2, cu3 = u3;
                    if (k4 < 31) {
                        const float* up = ubl + (k4 + 1) * 128;
                        x0 = hp0[k4 + 1]; x1 = hp1[k4 + 1];
                        x2 = hp2[k4 + 1]; x3 = hp3[k4 + 1];
                        u0 = up[0]; u1 = up[32]; u2 = up[64]; u3 = up[96];
                    }
                    a0.x = fmaf(cx0.x,cu0,a0.x); a0.y = fmaf(cx0.y,cu1,a0.y);
                    a0.z = fmaf(cx0.z,cu2,a0.z); a0.w = fmaf(cx0.w,cu3,a0.w);
                    a1.x = fmaf(cx1.x,cu0,a1.x); a1.y = fmaf(cx1.y,cu1,a1.y);
                    a1.z = fmaf(cx1.z,cu2,a1.z); a1.w = fmaf(cx1.w,cu3,a1.w);
                    a2.x = fmaf(cx2.x,cu0,a2.x); a2.y = fmaf(cx2.y,cu1,a2.y);
                    a2.z = fmaf(cx2.z,cu2,a2.z); a2.w = fmaf(cx2.w,cu3,a2.w);
                    a3.x = fmaf(cx3.x,cu0,a3.x); a3.y = fmaf(cx3.y,cu1,a3.y);
                    a3.z = fmaf(cx3.z,cu2,a3.z); a3.w = fmaf(cx3.w,cu3,a3.w);
                }
            }
            __syncthreads();
        }
        const float iv0 = (a0.x + a0.y) + (a0.z + a0.w);
        const float iv1 = (a1.x + a1.y) + (a1.z + a1.w);
        const float iv2 = (a2.x + a2.y) + (a2.z + a2.w);
        const float iv3 = (a3.x + a3.y) + (a3.z + a3.w);

        // ================= phase B =================
        float s0=0.f, s1=0.f, s2=0.f, s3=0.f;
        float q0=0.f, q1=0.f, q2=0.f, q3=0.f;

        #pragma unroll 1
        for (int c = 0; c < 8; ++c) {
            if (c < 7) {
                float4* dv = (float4*)(ubuf + ((c + 1) & 1) * 4096);
                #pragma unroll
                for (int i = 0; i < 4; ++i) {
                    const int idx = tid + i * 256;
                    const int r = idx >> 5, cc = idx & 31;
                    cp16(dv + idx, pv4 + r * 256 + (c + 1) * 32 + cc);
                }
                CP_COMMIT();
                CP_WAIT1();
            } else {
                CP_WAIT0();
            }
            __syncthreads();

            if (gvalid) {
                const float4* vb = (const float4*)(ubuf + (c & 1) * 4096);

                // prefetch residual h rows early (L2-hot from phase A staging)
                float4 hv0 = h4[(size_t)gt[0] * 256 + c * 32 + lane];
                float4 hv1 = h4[(size_t)gt[1] * 256 + c * 32 + lane];
                float4 hv2 = h4[(size_t)gt[2] * 256 + c * 32 + lane];
                float4 hv3 = h4[(size_t)gt[3] * 256 + c * 32 + lane];

                float4 p0 = make_float4(0.f,0.f,0.f,0.f);
                float4 p1 = make_float4(0.f,0.f,0.f,0.f);
                float4 p2 = make_float4(0.f,0.f,0.f,0.f);
                float4 p3 = make_float4(0.f,0.f,0.f,0.f);

                // 1-deep pipeline over r: prefetch v and shfl broadcasts
                float4 vn = vb[lane];
                float bn0 = __shfl_sync(0xffffffffu, iv0, 0);
                float bn1 = __shfl_sync(0xffffffffu, iv1, 0);
                float bn2 = __shfl_sync(0xffffffffu, iv2, 0);
                float bn3 = __shfl_sync(0xffffffffu, iv3, 0);

                #pragma unroll 4
                for (int r = 0; r < 32; ++r) {
                    float4 v = vn;
                    float b0 = bn0, b1 = bn1, b2 = bn2, b3 = bn3;
                    if (r < 31) {
                        vn = vb[(r + 1) * 32 + lane];
                        bn0 = __shfl_sync(0xffffffffu, iv0, r + 1);
                        bn1 = __shfl_sync(0xffffffffu, iv1, r + 1);
                        bn2 = __shfl_sync(0xffffffffu, iv2, r + 1);
                        bn3 = __shfl_sync(0xffffffffu, iv3, r + 1);
                    }
                    p0.x = fmaf(b0,v.x,p0.x); p0.y = fmaf(b0,v.y,p0.y);
                    p0.z = fmaf(b0,v.z,p0.z); p0.w = fmaf(b0,v.w,p0.w);
                    p1.x = fmaf(b1,v.x,p1.x); p1.y = fmaf(b1,v.y,p1.y);
                    p1.z = fmaf(b1,v.z,p1.z); p1.w = fmaf(b1,v.w,p1.w);
                    p2.x = fmaf(b2,v.x,p2.x); p2.y = fmaf(b2,v.y,p2.y);
                    p2.z = fmaf(b2,v.z,p2.z); p2.w = fmaf(b2,v.w,p2.w);
                    p3.x = fmaf(b3,v.x,p3.x); p3.y = fmaf(b3,v.y,p3.y);
                    p3.z = fmaf(b3,v.z,p3.z); p3.w = fmaf(b3,v.w,p3.w);
                }

                if (vd[0]) {
                    float4 d;
                    d.x = fmaf(alpha,p0.x,hv0.x); d.y = fmaf(alpha,p0.y,hv0.y);
                    d.z = fmaf(alpha,p0.z,hv0.z); d.w = fmaf(alpha,p0.w,hv0.w);
                    s0 += (d.x + d.y) + (d.z + d.w);
                    q0 += d.x*d.x + d.y*d.y + d.z*d.z + d.w*d.w;
                    out4[(size_t)gt[0] * 256 + c * 32 + lane] = d;
                }
                if (vd[1]) {
                    float4 d;
                    d.x = fmaf(alpha,p1.x,hv1.x); d.y = fmaf(alpha,p1.y,hv1.y);
                    d.z = fmaf(alpha,p1.z,hv1.z); d.w = fmaf(alpha,p1.w,hv1.w);
                    s1 += (d.x + d.y) + (d.z + d.w);
                    q1 += d.x*d.x + d.y*d.y + d.z*d.z + d.w*d.w;
                    out4[(size_t)gt[1] * 256 + c * 32 + lane] = d;
                }
                if (vd[2]) {
                    float4 d;
                    d.x = fmaf(alpha,p2.x,hv2.x); d.y = fmaf(alpha,p2.y,hv2.y);
                    d.z = fmaf(alpha,p2.z,hv2.z); d.w = fmaf(alpha,p2.w,hv2.w);
                    s2 += (d.x + d.y) + (d.z + d.w);
                    q2 += d.x*d.x + d.y*d.y + d.z*d.z + d.w*d.w;
                    out4[(size_t)gt[2] * 256 + c * 32 + lane] = d;
                }
                if (vd[3]) {
                    float4 d;
                    d.x = fmaf(alpha,p3.x,hv3.x); d.y = fmaf(alpha,p3.y,hv3.y);
                    d.z = fmaf(alpha,p3.z,hv3.z); d.w = fmaf(alpha,p3.w,hv3.w);
                    s3 += (d.x + d.y) + (d.z + d.w);
                    q3 += d.x*d.x + d.y*d.y + d.z*d.z + d.w*d.w;
                    out4[(size_t)gt[3] * 256 + c * 32 + lane] = d;
                }
            }
            __syncthreads();
        }

        // ---- LN finalize + normalize (valid groups only) ----
        if (gvalid) {
            #pragma unroll
            for (int o = 16; o > 0; o >>= 1) {
                s0 += __shfl_xor_sync(0xffffffffu, s0, o);
                q0 += __shfl_xor_sync(0xffffffffu, q0, o);
                s1 += __shfl_xor_sync(0xffffffffu, s1, o);
                q1 += __shfl_xor_sync(0xffffffffu, q1, o);
                s2 += __shfl_xor_sync(0xffffffffu, s2, o);
                q2 += __shfl_xor_sync(0xffffffffu, q2, o);
                s3 += __shfl_xor_sync(0xffffffffu, s3, o);
                q3 += __shfl_xor_sync(0xffffffffu, q3, o);
            }
            float mean[4], rstd[4];
            mean[0] = s0 * (1.0f/H_DIM);
            mean[1] = s1 * (1.0f/H_DIM);
            mean[2] = s2 * (1.0f/H_DIM);
            mean[3] = s3 * (1.0f/H_DIM);
            rstd[0] = rsqrtf(q0*(1.0f/H_DIM) - mean[0]*mean[0] + LN_EPS);
            rstd[1] = rsqrtf(q1*(1.0f/H_DIM) - mean[1]*mean[1] + LN_EPS);
            rstd[2] = rsqrtf(q2*(1.0f/H_DIM) - mean[2]*mean[2] + LN_EPS);
            rstd[3] = rsqrtf(q3*(1.0f/H_DIM) - mean[3]*mean[3] + LN_EPS);

            const float4* g4 = (const float4*)gamma;
            const float4* b4 = (const float4*)beta;
            #pragma unroll
            for (int i = 0; i < 4; ++i) {
                if (!vd[i]) continue;
                const float mn = mean[i], rs = rstd[i];
                float4* op = out4 + (size_t)gt[i] * 256 + lane;
                #pragma unroll
                for (int c = 0; c < 8; ++c) {
                    float4 d = op[c * 32];
                    float4 g = g4[c * 32 + lane];
                    float4 bb = b4[c * 32 + lane];
                    float4 o_;
                    o_.x = (d.x - mn) * rs * g.x + bb.x;
                    o_.y = (d.y - mn) * rs * g.y + bb.y;
                    o_.z = (d.z - mn) * rs * g.z + bb.z;
                    o_.w = (d.w - mn) * rs * g.w + bb.w;
                    op[c * 32] = o_;
                }
            }
        }
        __syncthreads();   // buffers/stoks reuse + s_item overwrite safety
    }
}

extern "C" void kernel_launch(void* const* d_in, const int* in_sizes, int n_in,
                              void* d_out, int out_size)
{
    const float* h     = (const float*)d_in[0];
    const float* la    = (const float*)d_in[1];
    const float* gamma = (const float*)d_in[2];
    const float* beta  = (const float*)d_in[3];
    const float* pu    = (const float*)d_in[4];
    const float* pv    = (const float*)d_in[5];
    const int*   ids   = (const int*)d_in[6];
    float*       out   = (float*)d_out;

    build_lists_kernel<<<(BTOK + 255) / 256, 256>>>(ids);
    build_items_kernel<<<1, NAG>>>();

    cudaFuncSetAttribute(div_inject_kernel,
                         cudaFuncAttributeMaxDynamicSharedMemorySize, SMEM_BYTES);
    div_inject_kernel<<<GRID_MAIN, NTH, SMEM_BYTES>>>(h, la, gamma, beta, pu, pv, out);
}